// round 1
// baseline (speedup 1.0000x reference)
#include <cuda_runtime.h>
#include <cuda_bf16.h>

// Problem constants (fixed-shape problem)
#define Nn 4096
#define Ee 8192
#define Hh 128
#define INF 64
#define Gg 8
#define STEPS 3
#define EHID 32
#define KO (EHID*Hh)          // 4096
#define W2_STEP (EHID*Hh*Hh)  // 32*16384 = 524288

// ---------------- device scratch (allocation-free rule) ----------------
__device__ float g_x[Nn*Hh];          // x == h (identical in this net)
__device__ float g_u[Nn*EHID*Hh];     // 64 MB
__device__ float g_v[Nn*Hh];
__device__ float g_eh[Ee*EHID];
__device__ float g_agg[Nn*Hh];
__device__ float g_m[Nn*Hh];
__device__ float g_gi[Nn*3*Hh];
__device__ float g_gh[Nn*3*Hh];
__device__ float g_deg[Nn];
__device__ float g_invdeg[Nn];
__device__ float g_pool[Gg*Hh];
__device__ float g_cnt[Gg];

// ---------------- utility ----------------
__global__ void zero_kernel(float* p, int n) {
    int i = blockIdx.x * blockDim.x + threadIdx.x;
    if (i < n) p[i] = 0.f;
}

// x = relu(x_in @ lin0_w + b); one block per node
__global__ void lin0_kernel(const float* __restrict__ xin,
                            const float* __restrict__ w,
                            const float* __restrict__ b) {
    int n = blockIdx.x;
    int j = threadIdx.x;
    __shared__ float xr[INF];
    if (j < INF) xr[j] = xin[n*INF + j];
    __syncthreads();
    float acc = b[j];
#pragma unroll
    for (int i = 0; i < INF; i++) acc = fmaf(xr[i], w[i*Hh + j], acc);
    g_x[n*Hh + j] = fmaxf(acc, 0.f);
}

__global__ void deg_kernel(const int* __restrict__ ei) {
    int e = blockIdx.x * blockDim.x + threadIdx.x;
    if (e < Ee) atomicAdd(&g_deg[ei[Ee + e]], 1.f);
}

__global__ void invdeg_kernel() {
    int n = blockIdx.x * blockDim.x + threadIdx.x;
    if (n < Nn) {
        float d = g_deg[n];
        g_invdeg[n] = (d > 0.f) ? (1.f / d) : 0.f;
    }
}

// e_h[e,k] = relu(edge_attr[e]*w1[k] + b1[k])
__global__ void edge_mlp_kernel(const float* __restrict__ ea,
                                const float* __restrict__ w1,
                                const float* __restrict__ b1) {
    int idx = blockIdx.x * blockDim.x + threadIdx.x;
    if (idx >= Ee*EHID) return;
    int e = idx >> 5, k = idx & 31;
    g_eh[idx] = fmaxf(fmaf(ea[e], w1[k], b1[k]), 0.f);
}

// ---------------- SGEMM 128x128 tile, K=128 fixed, NN layout ----------------
// B element (h, o_local) of column-tile bx lives at Bbase + bx*btile_stride + h*ldb + o_local
// C element (m, o_local) lives at C + m*ldc + bx*ctile_stride + o_local
// epi: 0 = plain store, 1 = root epilogue (relu(acc + bias[o] + agg[m,o]*invdeg[m]))
__global__ void __launch_bounds__(256)
gemm_nn(const float* __restrict__ A, const float* __restrict__ Bbase,
        float* __restrict__ C,
        int lda, int ldb, int btile_stride, int ldc, int ctile_stride,
        int epi, const float* __restrict__ bias) {
    const int bx = blockIdx.x;
    const int m0 = blockIdx.y * 128;
    const float* B = Bbase + (long)bx * btile_stride;
    const int tid = threadIdx.x;
    const int tx = tid & 15, ty = tid >> 4;

    __shared__ float As[8][128];
    __shared__ float Bs[8][128];

    float acc[8][8];
#pragma unroll
    for (int i = 0; i < 8; i++)
#pragma unroll
        for (int j = 0; j < 8; j++) acc[i][j] = 0.f;

    const int a_m = tid >> 1;
    const int a_k4 = (tid & 1) * 4;
    const int b_k = tid >> 5;
    const int b_n4 = (tid & 31) * 4;

    for (int k0 = 0; k0 < 128; k0 += 8) {
        float4 av = *(const float4*)(A + (long)(m0 + a_m)*lda + k0 + a_k4);
        float4 bv = *(const float4*)(B + (long)(k0 + b_k)*ldb + b_n4);
        As[a_k4 + 0][a_m] = av.x;
        As[a_k4 + 1][a_m] = av.y;
        As[a_k4 + 2][a_m] = av.z;
        As[a_k4 + 3][a_m] = av.w;
        *(float4*)(&Bs[b_k][b_n4]) = bv;
        __syncthreads();
#pragma unroll
        for (int k = 0; k < 8; k++) {
            float4 a0 = *(const float4*)(&As[k][ty*8]);
            float4 a1 = *(const float4*)(&As[k][ty*8 + 4]);
            float4 b0 = *(const float4*)(&Bs[k][tx*8]);
            float4 b1 = *(const float4*)(&Bs[k][tx*8 + 4]);
            float a[8] = {a0.x,a0.y,a0.z,a0.w,a1.x,a1.y,a1.z,a1.w};
            float b[8] = {b0.x,b0.y,b0.z,b0.w,b1.x,b1.y,b1.z,b1.w};
#pragma unroll
            for (int i = 0; i < 8; i++)
#pragma unroll
                for (int j = 0; j < 8; j++) acc[i][j] = fmaf(a[i], b[j], acc[i][j]);
        }
        __syncthreads();
    }

#pragma unroll
    for (int i = 0; i < 8; i++) {
        int m = m0 + ty*8 + i;
        float idg = (epi == 1) ? g_invdeg[m] : 0.f;
#pragma unroll
        for (int j = 0; j < 8; j++) {
            int n = tx*8 + j;
            float v = acc[i][j];
            if (epi == 1) {
                v += bias[n] + g_agg[(long)m*Hh + n] * idg;
                v = fmaxf(v, 0.f);
            }
            C[(long)m*ldc + (long)bx*ctile_stride + n] = v;
        }
    }
}

// ---------------- SGEMM TN for GRU: C[m, bx*128+j] = sum_h A[m,h]*W[(bx*128+j)*128+h] + bias ----
__global__ void __launch_bounds__(256)
gemm_tn(const float* __restrict__ A, const float* __restrict__ W,
        float* __restrict__ C, const float* __restrict__ bias) {
    const int bx = blockIdx.x;            // column tile (0..2), ldc=384
    const int m0 = blockIdx.y * 128;
    const int tid = threadIdx.x;
    const int tx = tid & 15, ty = tid >> 4;

    __shared__ float As[8][128];
    __shared__ float Bs[8][128];

    float acc[8][8];
#pragma unroll
    for (int i = 0; i < 8; i++)
#pragma unroll
        for (int j = 0; j < 8; j++) acc[i][j] = 0.f;

    const int a_m = tid >> 1;
    const int a_k4 = (tid & 1) * 4;
    const int b_j = tid >> 1;
    const int b_k4 = (tid & 1) * 4;

    for (int k0 = 0; k0 < 128; k0 += 8) {
        float4 av = *(const float4*)(A + (long)(m0 + a_m)*Hh + k0 + a_k4);
        float4 wv = *(const float4*)(W + (long)(bx*128 + b_j)*Hh + k0 + b_k4);
        As[a_k4 + 0][a_m] = av.x;
        As[a_k4 + 1][a_m] = av.y;
        As[a_k4 + 2][a_m] = av.z;
        As[a_k4 + 3][a_m] = av.w;
        Bs[b_k4 + 0][b_j] = wv.x;
        Bs[b_k4 + 1][b_j] = wv.y;
        Bs[b_k4 + 2][b_j] = wv.z;
        Bs[b_k4 + 3][b_j] = wv.w;
        __syncthreads();
#pragma unroll
        for (int k = 0; k < 8; k++) {
            float4 a0 = *(const float4*)(&As[k][ty*8]);
            float4 a1 = *(const float4*)(&As[k][ty*8 + 4]);
            float4 b0 = *(const float4*)(&Bs[k][tx*8]);
            float4 b1 = *(const float4*)(&Bs[k][tx*8 + 4]);
            float a[8] = {a0.x,a0.y,a0.z,a0.w,a1.x,a1.y,a1.z,a1.w};
            float b[8] = {b0.x,b0.y,b0.z,b0.w,b1.x,b1.y,b1.z,b1.w};
#pragma unroll
            for (int i = 0; i < 8; i++)
#pragma unroll
                for (int j = 0; j < 8; j++) acc[i][j] = fmaf(a[i], b[j], acc[i][j]);
        }
        __syncthreads();
    }

#pragma unroll
    for (int i = 0; i < 8; i++) {
        int m = m0 + ty*8 + i;
#pragma unroll
        for (int j = 0; j < 8; j++) {
            int n = tx*8 + j;
            C[(long)m*384 + bx*128 + n] = acc[i][j] + bias[bx*128 + n];
        }
    }
}

// ---------------- per-edge message + scatter ----------------
__global__ void msg_kernel(const int* __restrict__ ei) {
    int e = blockIdx.x;
    int o = threadIdx.x;                 // 0..127
    __shared__ float eh[EHID];
    __shared__ int rc[2];
    if (o < EHID) eh[o] = g_eh[e*EHID + o];
    if (o == 0) { rc[0] = ei[e]; rc[1] = ei[Ee + e]; }
    __syncthreads();
    int r = rc[0], c = rc[1];
    const float* up = g_u + (long)r * KO + o;
    float acc = g_v[r*Hh + o];
#pragma unroll
    for (int k = 0; k < EHID; k++) acc = fmaf(eh[k], up[k*Hh], acc);
    atomicAdd(&g_agg[c*Hh + o], acc);
}

// ---------------- GRU gates (elementwise), updates g_x in place (x == h) ----
__global__ void gru_gate_kernel() {
    int idx = blockIdx.x * blockDim.x + threadIdx.x;
    if (idx >= Nn*Hh) return;
    int n = idx >> 7, j = idx & 127;
    long base = (long)n * 384;
    float ir = g_gi[base + j],       hr = g_gh[base + j];
    float iz = g_gi[base + 128 + j], hz = g_gh[base + 128 + j];
    float in_ = g_gi[base + 256 + j], hn = g_gh[base + 256 + j];
    float r = 1.f / (1.f + expf(-(ir + hr)));
    float z = 1.f / (1.f + expf(-(iz + hz)));
    float nv = tanhf(in_ + r * hn);
    float h = g_x[idx];
    g_x[idx] = (1.f - z) * nv + z * h;
}

// ---------------- global mean pool ----------------
__global__ void pool_kernel(const int* __restrict__ batch) {
    int idx = blockIdx.x * blockDim.x + threadIdx.x;
    if (idx >= Nn*Hh) return;
    int n = idx >> 7, j = idx & 127;
    int b = batch[n];
    atomicAdd(&g_pool[b*Hh + j], g_x[idx]);
    if (j == 0) atomicAdd(&g_cnt[b], 1.f);
}

// ---------------- readout: [G,H] -> relu lin1 -> lin2 -> out[G] --------------
__global__ void readout_kernel(const float* __restrict__ lin1_w,
                               const float* __restrict__ lin1_b,
                               const float* __restrict__ lin2_w,
                               const float* __restrict__ lin2_b,
                               float* __restrict__ out) {
    __shared__ float gm[Gg*Hh];
    __shared__ float s1[Gg*64];
    int tid = threadIdx.x;               // 512 threads
    for (int i = tid; i < Gg*Hh; i += 512) {
        float c = g_cnt[i >> 7];
        gm[i] = g_pool[i] / fmaxf(c, 1.f);
    }
    __syncthreads();
    {
        int g = tid >> 6, j = tid & 63;
        float acc = lin1_b[j];
#pragma unroll 16
        for (int h = 0; h < Hh; h++) acc = fmaf(gm[g*Hh + h], lin1_w[h*64 + j], acc);
        s1[g*64 + j] = fmaxf(acc, 0.f);
    }
    __syncthreads();
    if (tid < Gg) {
        float acc = lin2_b[0];
#pragma unroll
        for (int j = 0; j < 64; j++) acc = fmaf(s1[tid*64 + j], lin2_w[j], acc);
        out[tid] = acc;
    }
}

// ---------------- host launcher ----------------
extern "C" void kernel_launch(void* const* d_in, const int* in_sizes, int n_in,
                              void* d_out, int out_size) {
    const float* x       = (const float*)d_in[0];
    const int*   ei      = (const int*)  d_in[1];
    const float* ea      = (const float*)d_in[2];
    const int*   batch   = (const int*)  d_in[3];
    const float* lin0_w  = (const float*)d_in[4];
    const float* lin0_b  = (const float*)d_in[5];
    const float* nn_w1   = (const float*)d_in[6];
    const float* nn_b1   = (const float*)d_in[7];
    const float* nn_w2   = (const float*)d_in[8];
    const float* nn_b2   = (const float*)d_in[9];
    const float* root_w  = (const float*)d_in[10];
    const float* conv_b  = (const float*)d_in[11];
    const float* gru_wih = (const float*)d_in[12];
    const float* gru_whh = (const float*)d_in[13];
    const float* gru_bih = (const float*)d_in[14];
    const float* gru_bhh = (const float*)d_in[15];
    const float* lin1_w  = (const float*)d_in[16];
    const float* lin1_b  = (const float*)d_in[17];
    const float* lin2_w  = (const float*)d_in[18];
    const float* lin2_b  = (const float*)d_in[19];
    float* out = (float*)d_out;

    float *p_x, *p_u, *p_v, *p_agg, *p_m, *p_gi, *p_gh, *p_deg, *p_pool, *p_cnt;
    cudaGetSymbolAddress((void**)&p_x,    g_x);
    cudaGetSymbolAddress((void**)&p_u,    g_u);
    cudaGetSymbolAddress((void**)&p_v,    g_v);
    cudaGetSymbolAddress((void**)&p_agg,  g_agg);
    cudaGetSymbolAddress((void**)&p_m,    g_m);
    cudaGetSymbolAddress((void**)&p_gi,   g_gi);
    cudaGetSymbolAddress((void**)&p_gh,   g_gh);
    cudaGetSymbolAddress((void**)&p_deg,  g_deg);
    cudaGetSymbolAddress((void**)&p_pool, g_pool);
    cudaGetSymbolAddress((void**)&p_cnt,  g_cnt);

    // init / degree
    zero_kernel<<<(Nn + 255)/256, 256>>>(p_deg, Nn);
    zero_kernel<<<(Gg*Hh + 255)/256, 256>>>(p_pool, Gg*Hh);
    zero_kernel<<<1, 32>>>(p_cnt, Gg);
    lin0_kernel<<<Nn, Hh>>>(x, lin0_w, lin0_b);
    deg_kernel<<<(Ee + 255)/256, 256>>>(ei);
    invdeg_kernel<<<(Nn + 255)/256, 256>>>();

    for (int t = 0; t < STEPS; t++) {
        // e_h
        edge_mlp_kernel<<<(Ee*EHID + 255)/256, 256>>>(ea, nn_w1 + t*EHID, nn_b1 + t*EHID);
        // u = x @ W2'  (per column-tile bx = k, B tile at nn_w2[t] + k*16384)
        gemm_nn<<<dim3(EHID, Nn/128), 256>>>(
            p_x, nn_w2 + (long)t*W2_STEP, p_u,
            Hh, Hh, Hh*Hh, KO, Hh, 0, nullptr);
        // v = x @ B2 (b2 reshaped [H,H])
        gemm_nn<<<dim3(1, Nn/128), 256>>>(
            p_x, nn_b2 + (long)t*Hh*Hh, p_v,
            Hh, Hh, Hh, Hh, Hh, 0, nullptr);
        // scatter messages
        zero_kernel<<<(Nn*Hh + 255)/256, 256>>>(p_agg, Nn*Hh);
        msg_kernel<<<Ee, Hh>>>(ei);
        // m = relu(agg*invdeg + x@root_w + conv_b)
        gemm_nn<<<dim3(1, Nn/128), 256>>>(
            p_x, root_w + (long)t*Hh*Hh, p_m,
            Hh, Hh, Hh, Hh, Hh, 1, conv_b + t*Hh);
        // GRU gates
        gemm_tn<<<dim3(3, Nn/128), 256>>>(p_m, gru_wih, p_gi, gru_bih);
        gemm_tn<<<dim3(3, Nn/128), 256>>>(p_x, gru_whh, p_gh, gru_bhh);
        gru_gate_kernel<<<(Nn*Hh + 255)/256, 256>>>();
    }

    pool_kernel<<<(Nn*Hh + 255)/256, 256>>>(batch);
    readout_kernel<<<1, 512>>>(lin1_w, lin1_b, lin2_w, lin2_b, out);
}

// round 3
// speedup vs baseline: 2.0878x; 2.0878x over previous
#include <cuda_runtime.h>
#include <cuda_bf16.h>
#include <cstdint>

// Problem constants
#define Nn 4096
#define Ee 8192
#define Hh 128
#define INF 64
#define Gg 8
#define STEPS 3
#define EHID 32
#define KO (EHID*Hh)          // 4096
#define TILE 16384            // 128x128 elements

// ---------------- device scratch (allocation-free rule) ----------------
__device__ float g_x[Nn*Hh];
__device__ float g_u[Nn*EHID*Hh];     // 64 MB fp32
__device__ float g_v[Nn*Hh];
__device__ float g_eh[Ee*EHID];
__device__ float g_agg[Nn*Hh];
__device__ float g_m[Nn*Hh];
__device__ float g_gi[Nn*3*Hh];
__device__ float g_gh[Nn*3*Hh];
__device__ float g_deg[Nn];
__device__ float g_invdeg[Nn];
__device__ float g_pool[Gg*Hh];
__device__ float g_cnt[Gg];

// bf16 split operands
__device__ __nv_bfloat16 g_xhi[Nn*Hh],  g_xlo[Nn*Hh];
__device__ __nv_bfloat16 g_mhi[Nn*Hh],  g_mlo[Nn*Hh];
__device__ __nv_bfloat16 g_w2t_hi[STEPS*EHID*TILE], g_w2t_lo[STEPS*EHID*TILE];
__device__ __nv_bfloat16 g_b2t_hi[STEPS*TILE], g_b2t_lo[STEPS*TILE];
__device__ __nv_bfloat16 g_rwt_hi[STEPS*TILE], g_rwt_lo[STEPS*TILE];
__device__ __nv_bfloat16 g_wih_hi[3*TILE], g_wih_lo[3*TILE];
__device__ __nv_bfloat16 g_whh_hi[3*TILE], g_whh_lo[3*TILE];

// ---------------- helpers ----------------
__device__ __forceinline__ uint32_t smem_u32(const void* p) {
    uint32_t a;
    asm("{ .reg .u64 t; cvta.to.shared.u64 t, %1; cvt.u32.u64 %0, t; }"
        : "=r"(a) : "l"(p));
    return a;
}

__device__ __forceinline__ void ldmx4(uint32_t* r, uint32_t addr) {
    asm volatile("ldmatrix.sync.aligned.m8n8.x4.shared.b16 {%0,%1,%2,%3}, [%4];"
        : "=r"(r[0]), "=r"(r[1]), "=r"(r[2]), "=r"(r[3]) : "r"(addr));
}
__device__ __forceinline__ void ldmx2(uint32_t* r, uint32_t addr) {
    asm volatile("ldmatrix.sync.aligned.m8n8.x2.shared.b16 {%0,%1}, [%2];"
        : "=r"(r[0]), "=r"(r[1]) : "r"(addr));
}
__device__ __forceinline__ void mma16816(float* d, const uint32_t* a, const uint32_t* b) {
    asm volatile(
        "mma.sync.aligned.m16n8k16.row.col.f32.bf16.bf16.f32 "
        "{%0,%1,%2,%3}, {%4,%5,%6,%7}, {%8,%9}, {%0,%1,%2,%3};"
        : "+f"(d[0]), "+f"(d[1]), "+f"(d[2]), "+f"(d[3])
        : "r"(a[0]), "r"(a[1]), "r"(a[2]), "r"(a[3]), "r"(b[0]), "r"(b[1]));
}

// ---------------- small kernels ----------------
__global__ void zero_kernel(float* p, int n) {
    int i = blockIdx.x * blockDim.x + threadIdx.x;
    if (i < n) p[i] = 0.f;
}

__global__ void lin0_kernel(const float* __restrict__ xin,
                            const float* __restrict__ w,
                            const float* __restrict__ b) {
    int n = blockIdx.x;
    int j = threadIdx.x;
    __shared__ float xr[INF];
    if (j < INF) xr[j] = xin[n*INF + j];
    __syncthreads();
    float acc = b[j];
#pragma unroll
    for (int i = 0; i < INF; i++) acc = fmaf(xr[i], w[i*Hh + j], acc);
    g_x[n*Hh + j] = fmaxf(acc, 0.f);
}

__global__ void deg_kernel(const int* __restrict__ ei) {
    int e = blockIdx.x * blockDim.x + threadIdx.x;
    if (e < Ee) atomicAdd(&g_deg[ei[Ee + e]], 1.f);
}

__global__ void invdeg_kernel() {
    int n = blockIdx.x * blockDim.x + threadIdx.x;
    if (n < Nn) {
        float d = g_deg[n];
        g_invdeg[n] = (d > 0.f) ? (1.f / d) : 0.f;
    }
}

__global__ void edge_mlp_kernel(const float* __restrict__ ea,
                                const float* __restrict__ w1,
                                const float* __restrict__ b1) {
    int idx = blockIdx.x * blockDim.x + threadIdx.x;
    if (idx >= Ee*EHID) return;
    int e = idx >> 5, k = idx & 31;
    g_eh[idx] = fmaxf(fmaf(ea[e], w1[k], b1[k]), 0.f);
}

// fp32 -> (hi, lo) bf16 split, elementwise
__global__ void split_kernel(const float* __restrict__ src,
                             __nv_bfloat16* __restrict__ hi,
                             __nv_bfloat16* __restrict__ lo, int n) {
    int i = blockIdx.x * blockDim.x + threadIdx.x;
    if (i >= n) return;
    float v = src[i];
    __nv_bfloat16 h = __float2bfloat16(v);
    hi[i] = h;
    lo[i] = __float2bfloat16(v - __bfloat162float(h));
}

// transpose 128x128 fp32 tiles -> bf16 hi/lo, dst[o][h] = src[h][o]
__global__ void transpose_split(const float* __restrict__ src,
                                __nv_bfloat16* __restrict__ dhi,
                                __nv_bfloat16* __restrict__ dlo) {
    __shared__ float t[32][33];
    long tt = blockIdx.x;
    int o0 = blockIdx.y * 32, h0 = blockIdx.z * 32;
    int tx = threadIdx.x, ty = threadIdx.y;
    t[ty][tx] = src[tt*TILE + (h0 + ty)*128 + o0 + tx];
    __syncthreads();
    float v = t[tx][ty];
    long di = tt*TILE + (long)(o0 + ty)*128 + h0 + tx;
    __nv_bfloat16 h = __float2bfloat16(v);
    dhi[di] = h;
    dlo[di] = __float2bfloat16(v - __bfloat162float(h));
}

// ---------------- mma.sync bf16x3 GEMM: C[128m x 128n] tile ----------------
// A: [4096,128] bf16 hi/lo row-major. B tiles: [n(128) x k(128)] bf16, tile bx
// at +bx*TILE. bf16x3: acc = AhBh + AhBl + AlBh (same fp32 accumulators).
// epi 0: C = acc (+bias);  epi 1: C = relu(acc + bias + agg*invdeg)
#define LDS 136
#define SMEM_MMA (4*128*LDS*2)

__global__ void __launch_bounds__(256)
gemm_mma(const __nv_bfloat16* __restrict__ ahi, const __nv_bfloat16* __restrict__ alo,
         const __nv_bfloat16* __restrict__ bhi_base, const __nv_bfloat16* __restrict__ blo_base,
         float* __restrict__ C, int ldc, int ctile,
         const float* __restrict__ bias, int bias_tile, int epi) {
    extern __shared__ __nv_bfloat16 sm[];
    const int bx = blockIdx.x;
    const int m0 = blockIdx.y * 128;
    const int tid = threadIdx.x, lane = tid & 31, wid = tid >> 5;
    const int wm = (wid & 1) * 64, wn = (wid >> 1) * 32;

    // smem buffers: Ah, Al, Bh, Bl — each 128 rows x LDS bf16
    {
        const __nv_bfloat16* src[4] = {
            ahi + (long)m0*128, alo + (long)m0*128,
            bhi_base + (long)bx*TILE, blo_base + (long)bx*TILE };
#pragma unroll
        for (int buf = 0; buf < 4; buf++) {
            __nv_bfloat16* dst = sm + buf*128*LDS;
            const __nv_bfloat16* s = src[buf];
            for (int i = tid; i < 2048; i += 256) {
                int r = i >> 4, c = i & 15;
                *(uint4*)(dst + r*LDS + c*8) = *(const uint4*)(s + r*128 + c*8);
            }
        }
    }
    __syncthreads();

    float acc[4][4][4];
#pragma unroll
    for (int i = 0; i < 4; i++)
#pragma unroll
        for (int j = 0; j < 4; j++)
#pragma unroll
            for (int k = 0; k < 4; k++) acc[i][j][k] = 0.f;

    const uint32_t sbase = smem_u32(sm);
    // A frag addr: row = wm + mt*16 + (lane&15), col = (lane>>4)*8
    const uint32_t aAddrH = sbase + (((wm + (lane & 15))*LDS + (lane >> 4)*8) << 1);
    const uint32_t aAddrL = aAddrH + 128*LDS*2;
    // B frag addr: row = wn + nt*8 + (lane&7), col = ((lane>>3)&1)*8
    const uint32_t bAddrH = sbase + 2*128*LDS*2 +
        (((wn + (lane & 7))*LDS + ((lane >> 3) & 1)*8) << 1);
    const uint32_t bAddrL = bAddrH + 128*LDS*2;

    for (int k0 = 0; k0 < 128; k0 += 16) {
        uint32_t aH[4][4], aL[4][4], bH[4][2], bL[4][2];
#pragma unroll
        for (int mt = 0; mt < 4; mt++) {
            uint32_t off = (mt*16*LDS + k0) << 1;
            ldmx4(aH[mt], aAddrH + off);
            ldmx4(aL[mt], aAddrL + off);
        }
#pragma unroll
        for (int nt = 0; nt < 4; nt++) {
            uint32_t off = (nt*8*LDS + k0) << 1;
            ldmx2(bH[nt], bAddrH + off);
            ldmx2(bL[nt], bAddrL + off);
        }
#pragma unroll
        for (int mt = 0; mt < 4; mt++)
#pragma unroll
            for (int nt = 0; nt < 4; nt++) {
                mma16816(acc[mt][nt], aH[mt], bH[nt]);
                mma16816(acc[mt][nt], aH[mt], bL[nt]);
                mma16816(acc[mt][nt], aL[mt], bH[nt]);
            }
    }

    // epilogue: thread holds (m = r0 / r0+8, n = c0, c0+1) per tile
    const int r0 = lane >> 2, c0 = (lane & 3) * 2;
#pragma unroll
    for (int mt = 0; mt < 4; mt++) {
#pragma unroll
        for (int half = 0; half < 2; half++) {
            long m = m0 + wm + mt*16 + r0 + half*8;
            float idg = (epi == 1) ? g_invdeg[m] : 0.f;
            float* cp = C + m*(long)ldc + (long)bx*ctile;
            const float* ap = (epi == 1) ? (g_agg + m*128) : nullptr;
#pragma unroll
            for (int nt = 0; nt < 4; nt++) {
                int n = wn + nt*8 + c0;
                float v0 = acc[mt][nt][half*2 + 0];
                float v1 = acc[mt][nt][half*2 + 1];
                if (bias) {
                    v0 += bias[(long)bx*bias_tile + n];
                    v1 += bias[(long)bx*bias_tile + n + 1];
                }
                if (epi == 1) {
                    v0 = fmaxf(fmaf(ap[n],     idg, v0), 0.f);
                    v1 = fmaxf(fmaf(ap[n + 1], idg, v1), 0.f);
                }
                cp[n]     = v0;
                cp[n + 1] = v1;
            }
        }
    }
}

// ---------------- per-edge message + scatter ----------------
__global__ void msg_kernel(const int* __restrict__ ei) {
    int e = blockIdx.x;
    int o = threadIdx.x;
    __shared__ float eh[EHID];
    __shared__ int rc[2];
    if (o < EHID) eh[o] = g_eh[e*EHID + o];
    if (o == 0) { rc[0] = ei[e]; rc[1] = ei[Ee + e]; }
    __syncthreads();
    int r = rc[0], c = rc[1];
    const float* up = g_u + (long)r * KO + o;
    float acc = g_v[r*Hh + o];
#pragma unroll
    for (int k = 0; k < EHID; k++) acc = fmaf(eh[k], up[k*Hh], acc);
    atomicAdd(&g_agg[c*Hh + o], acc);
}

// ---------------- GRU gates ----------------
__global__ void gru_gate_kernel() {
    int idx = blockIdx.x * blockDim.x + threadIdx.x;
    if (idx >= Nn*Hh) return;
    int n = idx >> 7, j = idx & 127;
    long base = (long)n * 384;
    float ir = g_gi[base + j],        hr = g_gh[base + j];
    float iz = g_gi[base + 128 + j],  hz = g_gh[base + 128 + j];
    float in_ = g_gi[base + 256 + j], hn = g_gh[base + 256 + j];
    float r = 1.f / (1.f + expf(-(ir + hr)));
    float z = 1.f / (1.f + expf(-(iz + hz)));
    float nv = tanhf(in_ + r * hn);
    float h = g_x[idx];
    g_x[idx] = (1.f - z) * nv + z * h;
}

// ---------------- pool + readout ----------------
__global__ void pool_kernel(const int* __restrict__ batch) {
    int idx = blockIdx.x * blockDim.x + threadIdx.x;
    if (idx >= Nn*Hh) return;
    int n = idx >> 7, j = idx & 127;
    int b = batch[n];
    atomicAdd(&g_pool[b*Hh + j], g_x[idx]);
    if (j == 0) atomicAdd(&g_cnt[b], 1.f);
}

__global__ void readout_kernel(const float* __restrict__ lin1_w,
                               const float* __restrict__ lin1_b,
                               const float* __restrict__ lin2_w,
                               const float* __restrict__ lin2_b,
                               float* __restrict__ out) {
    __shared__ float gm[Gg*Hh];
    __shared__ float s1[Gg*64];
    int tid = threadIdx.x;
    for (int i = tid; i < Gg*Hh; i += 512) {
        float c = g_cnt[i >> 7];
        gm[i] = g_pool[i] / fmaxf(c, 1.f);
    }
    __syncthreads();
    {
        int g = tid >> 6, j = tid & 63;
        float acc = lin1_b[j];
#pragma unroll 16
        for (int h = 0; h < Hh; h++) acc = fmaf(gm[g*Hh + h], lin1_w[h*64 + j], acc);
        s1[g*64 + j] = fmaxf(acc, 0.f);
    }
    __syncthreads();
    if (tid < Gg) {
        float acc = lin2_b[0];
#pragma unroll
        for (int j = 0; j < 64; j++) acc = fmaf(s1[tid*64 + j], lin2_w[j], acc);
        out[tid] = acc;
    }
}

// ---------------- host launcher ----------------
extern "C" void kernel_launch(void* const* d_in, const int* in_sizes, int n_in,
                              void* d_out, int out_size) {
    const float* x       = (const float*)d_in[0];
    const int*   ei      = (const int*)  d_in[1];
    const float* ea      = (const float*)d_in[2];
    const int*   batch   = (const int*)  d_in[3];
    const float* lin0_w  = (const float*)d_in[4];
    const float* lin0_b  = (const float*)d_in[5];
    const float* nn_w1   = (const float*)d_in[6];
    const float* nn_b1   = (const float*)d_in[7];
    const float* nn_w2   = (const float*)d_in[8];
    const float* nn_b2   = (const float*)d_in[9];
    const float* root_w  = (const float*)d_in[10];
    const float* conv_b  = (const float*)d_in[11];
    const float* gru_wih = (const float*)d_in[12];
    const float* gru_whh = (const float*)d_in[13];
    const float* gru_bih = (const float*)d_in[14];
    const float* gru_bhh = (const float*)d_in[15];
    const float* lin1_w  = (const float*)d_in[16];
    const float* lin1_b  = (const float*)d_in[17];
    const float* lin2_w  = (const float*)d_in[18];
    const float* lin2_b  = (const float*)d_in[19];
    float* out = (float*)d_out;

    float *p_x, *p_u, *p_v, *p_agg, *p_m, *p_gi, *p_gh, *p_deg, *p_pool, *p_cnt;
    cudaGetSymbolAddress((void**)&p_x,    g_x);
    cudaGetSymbolAddress((void**)&p_u,    g_u);
    cudaGetSymbolAddress((void**)&p_v,    g_v);
    cudaGetSymbolAddress((void**)&p_agg,  g_agg);
    cudaGetSymbolAddress((void**)&p_m,    g_m);
    cudaGetSymbolAddress((void**)&p_gi,   g_gi);
    cudaGetSymbolAddress((void**)&p_gh,   g_gh);
    cudaGetSymbolAddress((void**)&p_deg,  g_deg);
    cudaGetSymbolAddress((void**)&p_pool, g_pool);
    cudaGetSymbolAddress((void**)&p_cnt,  g_cnt);

    __nv_bfloat16 *p_xhi, *p_xlo, *p_mhi, *p_mlo;
    __nv_bfloat16 *p_w2t_hi, *p_w2t_lo, *p_b2t_hi, *p_b2t_lo;
    __nv_bfloat16 *p_rwt_hi, *p_rwt_lo, *p_wih_hi, *p_wih_lo, *p_whh_hi, *p_whh_lo;
    cudaGetSymbolAddress((void**)&p_xhi, g_xhi);
    cudaGetSymbolAddress((void**)&p_xlo, g_xlo);
    cudaGetSymbolAddress((void**)&p_mhi, g_mhi);
    cudaGetSymbolAddress((void**)&p_mlo, g_mlo);
    cudaGetSymbolAddress((void**)&p_w2t_hi, g_w2t_hi);
    cudaGetSymbolAddress((void**)&p_w2t_lo, g_w2t_lo);
    cudaGetSymbolAddress((void**)&p_b2t_hi, g_b2t_hi);
    cudaGetSymbolAddress((void**)&p_b2t_lo, g_b2t_lo);
    cudaGetSymbolAddress((void**)&p_rwt_hi, g_rwt_hi);
    cudaGetSymbolAddress((void**)&p_rwt_lo, g_rwt_lo);
    cudaGetSymbolAddress((void**)&p_wih_hi, g_wih_hi);
    cudaGetSymbolAddress((void**)&p_wih_lo, g_wih_lo);
    cudaGetSymbolAddress((void**)&p_whh_hi, g_whh_hi);
    cudaGetSymbolAddress((void**)&p_whh_lo, g_whh_lo);

    cudaFuncSetAttribute(gemm_mma, cudaFuncAttributeMaxDynamicSharedMemorySize, SMEM_MMA);

    // init / degree / weight prep
    zero_kernel<<<(Nn + 255)/256, 256>>>(p_deg, Nn);
    zero_kernel<<<(Gg*Hh + 255)/256, 256>>>(p_pool, Gg*Hh);
    zero_kernel<<<1, 32>>>(p_cnt, Gg);
    lin0_kernel<<<Nn, Hh>>>(x, lin0_w, lin0_b);
    deg_kernel<<<(Ee + 255)/256, 256>>>(ei);
    invdeg_kernel<<<(Nn + 255)/256, 256>>>();

    transpose_split<<<dim3(STEPS*EHID, 4, 4), dim3(32, 32)>>>(nn_w2, p_w2t_hi, p_w2t_lo);
    transpose_split<<<dim3(STEPS, 4, 4),      dim3(32, 32)>>>(nn_b2, p_b2t_hi, p_b2t_lo);
    transpose_split<<<dim3(STEPS, 4, 4),      dim3(32, 32)>>>(root_w, p_rwt_hi, p_rwt_lo);
    split_kernel<<<(3*TILE + 255)/256, 256>>>(gru_wih, p_wih_hi, p_wih_lo, 3*TILE);
    split_kernel<<<(3*TILE + 255)/256, 256>>>(gru_whh, p_whh_hi, p_whh_lo, 3*TILE);

    for (int t = 0; t < STEPS; t++) {
        split_kernel<<<(Nn*Hh + 255)/256, 256>>>(p_x, p_xhi, p_xlo, Nn*Hh);
        edge_mlp_kernel<<<(Ee*EHID + 255)/256, 256>>>(ea, nn_w1 + t*EHID, nn_b1 + t*EHID);

        // u = x @ W2'  (32 n-tiles)
        gemm_mma<<<dim3(EHID, Nn/128), 256, SMEM_MMA>>>(
            p_xhi, p_xlo, p_w2t_hi + (long)t*EHID*TILE, p_w2t_lo + (long)t*EHID*TILE,
            p_u, KO, Hh, nullptr, 0, 0);
        // v = x @ B2
        gemm_mma<<<dim3(1, Nn/128), 256, SMEM_MMA>>>(
            p_xhi, p_xlo, p_b2t_hi + (long)t*TILE, p_b2t_lo + (long)t*TILE,
            p_v, Hh, Hh, nullptr, 0, 0);

        zero_kernel<<<(Nn*Hh + 255)/256, 256>>>(p_agg, Nn*Hh);
        msg_kernel<<<Ee, Hh>>>(ei);

        // m = relu(agg*invdeg + x@root_w + conv_b)
        gemm_mma<<<dim3(1, Nn/128), 256, SMEM_MMA>>>(
            p_xhi, p_xlo, p_rwt_hi + (long)t*TILE, p_rwt_lo + (long)t*TILE,
            p_m, Hh, Hh, conv_b + t*Hh, 0, 1);
        split_kernel<<<(Nn*Hh + 255)/256, 256>>>(p_m, p_mhi, p_mlo, Nn*Hh);

        // GRU gates
        gemm_mma<<<dim3(3, Nn/128), 256, SMEM_MMA>>>(
            p_mhi, p_mlo, p_wih_hi, p_wih_lo,
            p_gi, 3*Hh, Hh, gru_bih, Hh, 0);
        gemm_mma<<<dim3(3, Nn/128), 256, SMEM_MMA>>>(
            p_xhi, p_xlo, p_whh_hi, p_whh_lo,
            p_gh, 3*Hh, Hh, gru_bhh, Hh, 0);
        gru_gate_kernel<<<(Nn*Hh + 255)/256, 256>>>();
    }

    pool_kernel<<<(Nn*Hh + 255)/256, 256>>>(batch);
    readout_kernel<<<1, 512>>>(lin1_w, lin1_b, lin2_w, lin2_b, out);
}

// round 4
// speedup vs baseline: 2.1791x; 1.0437x over previous
#include <cuda_runtime.h>
#include <cuda_bf16.h>
#include <cstdint>

// Problem constants
#define Nn 4096
#define Ee 8192
#define Hh 128
#define INF 64
#define Gg 8
#define STEPS 3
#define EHID 32
#define KO (EHID*Hh)          // 4096
#define TILE 16384            // 128x128 elements

// ---------------- device scratch ----------------
__device__ float g_x[Nn*Hh];
__device__ float g_u[Nn*EHID*Hh];     // 64 MB fp32
__device__ float g_v[Nn*Hh];
__device__ float g_agg[Nn*Hh];
__device__ float g_gi[Nn*3*Hh];
__device__ float g_gh[Nn*3*Hh];
__device__ float g_invdeg[Nn];
__device__ float g_pool[Gg*Hh];
__device__ float g_cnt[Gg];
__device__ float g_degf[Nn];

// CSR by source row
__device__ int g_outc[Nn];
__device__ int g_cur[Nn];
__device__ int g_off[Nn + 1];
__device__ int g_csr[Ee];

// bf16 split operands
__device__ __nv_bfloat16 g_xhi[Nn*Hh],  g_xlo[Nn*Hh];
__device__ __nv_bfloat16 g_mhi[Nn*Hh],  g_mlo[Nn*Hh];
__device__ __nv_bfloat16 g_w2t_hi[STEPS*EHID*TILE], g_w2t_lo[STEPS*EHID*TILE];
__device__ __nv_bfloat16 g_b2t_hi[STEPS*TILE], g_b2t_lo[STEPS*TILE];
__device__ __nv_bfloat16 g_rwt_hi[STEPS*TILE], g_rwt_lo[STEPS*TILE];
__device__ __nv_bfloat16 g_wih_hi[3*TILE], g_wih_lo[3*TILE];
__device__ __nv_bfloat16 g_whh_hi[3*TILE], g_whh_lo[3*TILE];

// ---------------- helpers ----------------
__device__ __forceinline__ uint32_t smem_u32(const void* p) {
    uint32_t a;
    asm("{ .reg .u64 t; cvta.to.shared.u64 t, %1; cvt.u32.u64 %0, t; }"
        : "=r"(a) : "l"(p));
    return a;
}
__device__ __forceinline__ void ldmx4(uint32_t* r, uint32_t addr) {
    asm volatile("ldmatrix.sync.aligned.m8n8.x4.shared.b16 {%0,%1,%2,%3}, [%4];"
        : "=r"(r[0]), "=r"(r[1]), "=r"(r[2]), "=r"(r[3]) : "r"(addr));
}
__device__ __forceinline__ void ldmx2(uint32_t* r, uint32_t addr) {
    asm volatile("ldmatrix.sync.aligned.m8n8.x2.shared.b16 {%0,%1}, [%2];"
        : "=r"(r[0]), "=r"(r[1]) : "r"(addr));
}
__device__ __forceinline__ void mma16816(float* d, const uint32_t* a, const uint32_t* b) {
    asm volatile(
        "mma.sync.aligned.m16n8k16.row.col.f32.bf16.bf16.f32 "
        "{%0,%1,%2,%3}, {%4,%5,%6,%7}, {%8,%9}, {%0,%1,%2,%3};"
        : "+f"(d[0]), "+f"(d[1]), "+f"(d[2]), "+f"(d[3])
        : "r"(a[0]), "r"(a[1]), "r"(a[2]), "r"(a[3]), "r"(b[0]), "r"(b[1]));
}

// ---------------- GEMM core (128x128, K=128, bf16x3) ----------------
#define LDS 136
#define SMEM_MMA (4*128*LDS*2)

__device__ __forceinline__ void gemm_core(
        const __nv_bfloat16* __restrict__ ahi, const __nv_bfloat16* __restrict__ alo,
        const __nv_bfloat16* __restrict__ bhi, const __nv_bfloat16* __restrict__ blo,
        __nv_bfloat16* sm, float acc[4][4][4]) {
    const int tid = threadIdx.x, lane = tid & 31, wid = tid >> 5;
    const int wm = (wid & 1) * 64, wn = (wid >> 1) * 32;

    const __nv_bfloat16* src[4] = { ahi, alo, bhi, blo };
#pragma unroll
    for (int buf = 0; buf < 4; buf++) {
        __nv_bfloat16* dst = sm + buf*128*LDS;
        const __nv_bfloat16* s = src[buf];
        for (int i = tid; i < 2048; i += 256) {
            int r = i >> 4, c = i & 15;
            *(uint4*)(dst + r*LDS + c*8) = *(const uint4*)(s + r*128 + c*8);
        }
    }
    __syncthreads();

#pragma unroll
    for (int i = 0; i < 4; i++)
#pragma unroll
        for (int j = 0; j < 4; j++)
#pragma unroll
            for (int k = 0; k < 4; k++) acc[i][j][k] = 0.f;

    const uint32_t sbase = smem_u32(sm);
    const uint32_t aAddrH = sbase + (((wm + (lane & 15))*LDS + (lane >> 4)*8) << 1);
    const uint32_t aAddrL = aAddrH + 128*LDS*2;
    const uint32_t bAddrH = sbase + 2*128*LDS*2 +
        (((wn + (lane & 7))*LDS + ((lane >> 3) & 1)*8) << 1);
    const uint32_t bAddrL = bAddrH + 128*LDS*2;

    for (int k0 = 0; k0 < 128; k0 += 16) {
        uint32_t aH[4][4], aL[4][4], bH[4][2], bL[4][2];
#pragma unroll
        for (int mt = 0; mt < 4; mt++) {
            uint32_t off = (mt*16*LDS + k0) << 1;
            ldmx4(aH[mt], aAddrH + off);
            ldmx4(aL[mt], aAddrL + off);
        }
#pragma unroll
        for (int nt = 0; nt < 4; nt++) {
            uint32_t off = (nt*8*LDS + k0) << 1;
            ldmx2(bH[nt], bAddrH + off);
            ldmx2(bL[nt], bAddrL + off);
        }
#pragma unroll
        for (int mt = 0; mt < 4; mt++)
#pragma unroll
            for (int nt = 0; nt < 4; nt++) {
                mma16816(acc[mt][nt], aH[mt], bH[nt]);
                mma16816(acc[mt][nt], aH[mt], bL[nt]);
                mma16816(acc[mt][nt], aL[mt], bH[nt]);
            }
    }
}

// big fused GEMM per step: bx<32 -> u tiles; bx==32 -> v (+agg zero); bx 33..35 -> gh
__global__ void __launch_bounds__(256)
gemm_step1(int t, const float* __restrict__ bhh) {
    extern __shared__ __nv_bfloat16 sm[];
    const int bx = blockIdx.x;
    const int m0 = blockIdx.y * 128;
    const int tid = threadIdx.x, lane = tid & 31, wid = tid >> 5;
    const int wm = (wid & 1) * 64, wn = (wid >> 1) * 32;

    const __nv_bfloat16 *bhi, *blo;
    if (bx < 32) {
        bhi = g_w2t_hi + ((long)t*EHID + bx)*TILE;
        blo = g_w2t_lo + ((long)t*EHID + bx)*TILE;
    } else if (bx == 32) {
        bhi = g_b2t_hi + (long)t*TILE;
        blo = g_b2t_lo + (long)t*TILE;
    } else {
        bhi = g_whh_hi + (long)(bx - 33)*TILE;
        blo = g_whh_lo + (long)(bx - 33)*TILE;
    }

    float acc[4][4][4];
    gemm_core(g_xhi + (long)m0*128, g_xlo + (long)m0*128, bhi, blo, sm, acc);

    const int r0 = lane >> 2, c0 = (lane & 3) * 2;
#pragma unroll
    for (int mt = 0; mt < 4; mt++) {
#pragma unroll
        for (int half = 0; half < 2; half++) {
            long m = m0 + wm + mt*16 + r0 + half*8;
#pragma unroll
            for (int nt = 0; nt < 4; nt++) {
                int n = wn + nt*8 + c0;
                float v0 = acc[mt][nt][half*2 + 0];
                float v1 = acc[mt][nt][half*2 + 1];
                if (bx < 32) {
                    float* cp = g_u + m*KO + bx*128 + n;
                    cp[0] = v0; cp[1] = v1;
                } else if (bx == 32) {
                    float* cp = g_v + m*128 + n;
                    cp[0] = v0; cp[1] = v1;
                } else {
                    int g = bx - 33;
                    float* cp = g_gh + m*384 + g*128 + n;
                    cp[0] = v0 + bhh[g*128 + n];
                    cp[1] = v1 + bhh[g*128 + n + 1];
                }
            }
        }
    }
    // the v-CTA also zeroes agg for its m-block (runs before msg)
    if (bx == 32) {
        float4 z = {0.f, 0.f, 0.f, 0.f};
        float4* ap = (float4*)(g_agg + (long)m0*128);
        for (int i = tid; i < 4096; i += 256) ap[i] = z;
    }
}

// m = relu(agg*invdeg + x@root + conv_b); writes bf16 hi/lo splits only
__global__ void __launch_bounds__(256)
gemm_m(int t, const float* __restrict__ convb) {
    extern __shared__ __nv_bfloat16 sm[];
    const int m0 = blockIdx.y * 128;
    const int tid = threadIdx.x, lane = tid & 31, wid = tid >> 5;
    const int wm = (wid & 1) * 64, wn = (wid >> 1) * 32;

    float acc[4][4][4];
    gemm_core(g_xhi + (long)m0*128, g_xlo + (long)m0*128,
              g_rwt_hi + (long)t*TILE, g_rwt_lo + (long)t*TILE, sm, acc);

    const int r0 = lane >> 2, c0 = (lane & 3) * 2;
#pragma unroll
    for (int mt = 0; mt < 4; mt++) {
#pragma unroll
        for (int half = 0; half < 2; half++) {
            long m = m0 + wm + mt*16 + r0 + half*8;
            float idg = g_invdeg[m];
#pragma unroll
            for (int nt = 0; nt < 4; nt++) {
                int n = wn + nt*8 + c0;
                float v0 = fmaxf(fmaf(g_agg[m*128 + n],     idg,
                                      acc[mt][nt][half*2+0] + convb[n]), 0.f);
                float v1 = fmaxf(fmaf(g_agg[m*128 + n + 1], idg,
                                      acc[mt][nt][half*2+1] + convb[n+1]), 0.f);
                __nv_bfloat16 h0 = __float2bfloat16(v0);
                __nv_bfloat16 h1 = __float2bfloat16(v1);
                g_mhi[m*128 + n]     = h0;
                g_mhi[m*128 + n + 1] = h1;
                g_mlo[m*128 + n]     = __float2bfloat16(v0 - __bfloat162float(h0));
                g_mlo[m*128 + n + 1] = __float2bfloat16(v1 - __bfloat162float(h1));
            }
        }
    }
}

// gi = m @ wih^T + bih
__global__ void __launch_bounds__(256)
gemm_gi(const float* __restrict__ bih) {
    extern __shared__ __nv_bfloat16 sm[];
    const int bx = blockIdx.x;
    const int m0 = blockIdx.y * 128;
    const int tid = threadIdx.x, lane = tid & 31, wid = tid >> 5;
    const int wm = (wid & 1) * 64, wn = (wid >> 1) * 32;

    float acc[4][4][4];
    gemm_core(g_mhi + (long)m0*128, g_mlo + (long)m0*128,
              g_wih_hi + (long)bx*TILE, g_wih_lo + (long)bx*TILE, sm, acc);

    const int r0 = lane >> 2, c0 = (lane & 3) * 2;
#pragma unroll
    for (int mt = 0; mt < 4; mt++) {
#pragma unroll
        for (int half = 0; half < 2; half++) {
            long m = m0 + wm + mt*16 + r0 + half*8;
#pragma unroll
            for (int nt = 0; nt < 4; nt++) {
                int n = wn + nt*8 + c0;
                g_gi[m*384 + bx*128 + n]     = acc[mt][nt][half*2+0] + bih[bx*128 + n];
                g_gi[m*384 + bx*128 + n + 1] = acc[mt][nt][half*2+1] + bih[bx*128 + n + 1];
            }
        }
    }
}

// ---------------- prep kernels ----------------
__global__ void zero_misc() {
    int i = blockIdx.x * blockDim.x + threadIdx.x;
    if (i < Nn) { g_degf[i] = 0.f; g_outc[i] = 0; g_cur[i] = 0; }
    if (i < Gg*Hh) g_pool[i] = 0.f;
    if (i < Gg) g_cnt[i] = 0.f;
}

__global__ void lin0_kernel(const float* __restrict__ xin,
                            const float* __restrict__ w,
                            const float* __restrict__ b) {
    int n = blockIdx.x;
    int j = threadIdx.x;
    __shared__ float xr[INF];
    if (j < INF) xr[j] = xin[n*INF + j];
    __syncthreads();
    float acc = b[j];
#pragma unroll
    for (int i = 0; i < INF; i++) acc = fmaf(xr[i], w[i*Hh + j], acc);
    acc = fmaxf(acc, 0.f);
    g_x[n*Hh + j] = acc;
    __nv_bfloat16 h = __float2bfloat16(acc);
    g_xhi[n*Hh + j] = h;
    g_xlo[n*Hh + j] = __float2bfloat16(acc - __bfloat162float(h));
}

__global__ void hist_kernel(const int* __restrict__ ei) {
    int e = blockIdx.x * blockDim.x + threadIdx.x;
    if (e < Ee) {
        atomicAdd(&g_degf[ei[Ee + e]], 1.f);   // in-degree (target)
        atomicAdd(&g_outc[ei[e]], 1);          // out-degree (source)
    }
}

__global__ void scan_kernel() {   // 1 block, 1024 threads, 4096 elements
    __shared__ int s[1024];
    int tid = threadIdx.x;
    int base = tid * 4;
    int a0 = g_outc[base], a1 = g_outc[base+1], a2 = g_outc[base+2], a3 = g_outc[base+3];
    int sum = a0 + a1 + a2 + a3;
    s[tid] = sum;
    __syncthreads();
    for (int d = 1; d < 1024; d <<= 1) {
        int v = (tid >= d) ? s[tid - d] : 0;
        __syncthreads();
        s[tid] += v;
        __syncthreads();
    }
    int excl = s[tid] - sum;
    g_off[base]     = excl;
    g_off[base + 1] = excl + a0;
    g_off[base + 2] = excl + a0 + a1;
    g_off[base + 3] = excl + a0 + a1 + a2;
    if (tid == 1023) g_off[Nn] = excl + sum;
}

__global__ void scatter_kernel(const int* __restrict__ ei) {
    int e = blockIdx.x * blockDim.x + threadIdx.x;
    if (e < Ee) {
        int r = ei[e];
        int p = atomicAdd(&g_cur[r], 1);
        g_csr[g_off[r] + p] = e;
    }
}

__global__ void invdeg_kernel(const int* __restrict__ batch) {
    int n = blockIdx.x * blockDim.x + threadIdx.x;
    if (n < Nn) {
        float d = g_degf[n];
        g_invdeg[n] = (d > 0.f) ? (1.f / d) : 0.f;
        atomicAdd(&g_cnt[batch[n]], 1.f);
    }
}

// fp32 -> (hi, lo) bf16 split
__global__ void split_kernel(const float* __restrict__ src,
                             __nv_bfloat16* __restrict__ hi,
                             __nv_bfloat16* __restrict__ lo, int n) {
    int i = blockIdx.x * blockDim.x + threadIdx.x;
    if (i >= n) return;
    float v = src[i];
    __nv_bfloat16 h = __float2bfloat16(v);
    hi[i] = h;
    lo[i] = __float2bfloat16(v - __bfloat162float(h));
}

// transpose 128x128 fp32 tiles -> bf16 hi/lo, dst[o][h] = src[h][o]
__global__ void transpose_split(const float* __restrict__ src,
                                __nv_bfloat16* __restrict__ dhi,
                                __nv_bfloat16* __restrict__ dlo) {
    __shared__ float t[32][33];
    long tt = blockIdx.x;
    int o0 = blockIdx.y * 32, h0 = blockIdx.z * 32;
    int tx = threadIdx.x, ty = threadIdx.y;
    t[ty][tx] = src[tt*TILE + (h0 + ty)*128 + o0 + tx];
    __syncthreads();
    float v = t[tx][ty];
    long di = tt*TILE + (long)(o0 + ty)*128 + h0 + tx;
    __nv_bfloat16 h = __float2bfloat16(v);
    dhi[di] = h;
    dlo[di] = __float2bfloat16(v - __bfloat162float(h));
}

// ---------------- per-source message + scatter (CSR) ----------------
__global__ void msg_kernel(const int* __restrict__ ei, const float* __restrict__ ea,
                           const float* __restrict__ w1, const float* __restrict__ b1) {
    int r = blockIdx.x;
    int o = threadIdx.x;                 // 128
    int s0 = g_off[r], s1 = g_off[r + 1];
    if (s0 == s1) return;
    __shared__ float us[KO];             // 16 KB
    __shared__ float w1s[EHID], b1s[EHID];
    if (o < EHID) { w1s[o] = w1[o]; b1s[o] = b1[o]; }
    {
        const float4* up = (const float4*)(g_u + (long)r*KO);
        float4* usp = (float4*)us;
        for (int i = o; i < KO/4; i += 128) usp[i] = up[i];
    }
    float v = g_v[r*Hh + o];
    __syncthreads();
    for (int idx = s0; idx < s1; idx++) {
        int e = g_csr[idx];
        float a = ea[e];
        int c = ei[Ee + e];
        float acc = v;
#pragma unroll
        for (int k = 0; k < EHID; k++) {
            float ehk = fmaxf(fmaf(a, w1s[k], b1s[k]), 0.f);
            acc = fmaf(ehk, us[k*Hh + o], acc);
        }
        atomicAdd(&g_agg[c*Hh + o], acc);
    }
}

// ---------------- GRU gates (+split, +pool on last step) ----------------
__global__ void gate_kernel(const int* __restrict__ batch, int last) {
    int idx = blockIdx.x * blockDim.x + threadIdx.x;
    if (idx >= Nn*Hh) return;
    int n = idx >> 7, j = idx & 127;
    long base = (long)n * 384;
    float ir = g_gi[base + j],        hr = g_gh[base + j];
    float iz = g_gi[base + 128 + j],  hz = g_gh[base + 128 + j];
    float in_ = g_gi[base + 256 + j], hn = g_gh[base + 256 + j];
    float r = 1.f / (1.f + expf(-(ir + hr)));
    float z = 1.f / (1.f + expf(-(iz + hz)));
    float nv = tanhf(in_ + r * hn);
    float h = g_x[idx];
    float nx = (1.f - z) * nv + z * h;
    g_x[idx] = nx;
    __nv_bfloat16 hi = __float2bfloat16(nx);
    g_xhi[idx] = hi;
    g_xlo[idx] = __float2bfloat16(nx - __bfloat162float(hi));
    if (last) atomicAdd(&g_pool[batch[n]*Hh + j], nx);
}

// ---------------- readout ----------------
__global__ void readout_kernel(const float* __restrict__ lin1_w,
                               const float* __restrict__ lin1_b,
                               const float* __restrict__ lin2_w,
                               const float* __restrict__ lin2_b,
                               float* __restrict__ out) {
    __shared__ float gm[Gg*Hh];
    __shared__ float s1[Gg*64];
    int tid = threadIdx.x;
    for (int i = tid; i < Gg*Hh; i += 512) {
        float c = g_cnt[i >> 7];
        gm[i] = g_pool[i] / fmaxf(c, 1.f);
    }
    __syncthreads();
    {
        int g = tid >> 6, j = tid & 63;
        float acc = lin1_b[j];
#pragma unroll 16
        for (int h = 0; h < Hh; h++) acc = fmaf(gm[g*Hh + h], lin1_w[h*64 + j], acc);
        s1[g*64 + j] = fmaxf(acc, 0.f);
    }
    __syncthreads();
    if (tid < Gg) {
        float acc = lin2_b[0];
#pragma unroll
        for (int j = 0; j < 64; j++) acc = fmaf(s1[tid*64 + j], lin2_w[j], acc);
        out[tid] = acc;
    }
}

// ---------------- host launcher ----------------
extern "C" void kernel_launch(void* const* d_in, const int* in_sizes, int n_in,
                              void* d_out, int out_size) {
    const float* x       = (const float*)d_in[0];
    const int*   ei      = (const int*)  d_in[1];
    const float* ea      = (const float*)d_in[2];
    const int*   batch   = (const int*)  d_in[3];
    const float* lin0_w  = (const float*)d_in[4];
    const float* lin0_b  = (const float*)d_in[5];
    const float* nn_w1   = (const float*)d_in[6];
    const float* nn_b1   = (const float*)d_in[7];
    const float* nn_w2   = (const float*)d_in[8];
    const float* nn_b2   = (const float*)d_in[9];
    const float* root_w  = (const float*)d_in[10];
    const float* conv_b  = (const float*)d_in[11];
    const float* gru_wih = (const float*)d_in[12];
    const float* gru_whh = (const float*)d_in[13];
    const float* gru_bih = (const float*)d_in[14];
    const float* gru_bhh = (const float*)d_in[15];
    const float* lin1_w  = (const float*)d_in[16];
    const float* lin1_b  = (const float*)d_in[17];
    const float* lin2_w  = (const float*)d_in[18];
    const float* lin2_b  = (const float*)d_in[19];
    float* out = (float*)d_out;

    __nv_bfloat16 *p_w2t_hi, *p_w2t_lo, *p_b2t_hi, *p_b2t_lo;
    __nv_bfloat16 *p_rwt_hi, *p_rwt_lo, *p_wih_hi, *p_wih_lo, *p_whh_hi, *p_whh_lo;
    cudaGetSymbolAddress((void**)&p_w2t_hi, g_w2t_hi);
    cudaGetSymbolAddress((void**)&p_w2t_lo, g_w2t_lo);
    cudaGetSymbolAddress((void**)&p_b2t_hi, g_b2t_hi);
    cudaGetSymbolAddress((void**)&p_b2t_lo, g_b2t_lo);
    cudaGetSymbolAddress((void**)&p_rwt_hi, g_rwt_hi);
    cudaGetSymbolAddress((void**)&p_rwt_lo, g_rwt_lo);
    cudaGetSymbolAddress((void**)&p_wih_hi, g_wih_hi);
    cudaGetSymbolAddress((void**)&p_wih_lo, g_wih_lo);
    cudaGetSymbolAddress((void**)&p_whh_hi, g_whh_hi);
    cudaGetSymbolAddress((void**)&p_whh_lo, g_whh_lo);

    cudaFuncSetAttribute(gemm_step1, cudaFuncAttributeMaxDynamicSharedMemorySize, SMEM_MMA);
    cudaFuncSetAttribute(gemm_m,     cudaFuncAttributeMaxDynamicSharedMemorySize, SMEM_MMA);
    cudaFuncSetAttribute(gemm_gi,    cudaFuncAttributeMaxDynamicSharedMemorySize, SMEM_MMA);

    // prep
    zero_misc<<<(Nn + 255)/256, 256>>>();
    lin0_kernel<<<Nn, Hh>>>(x, lin0_w, lin0_b);
    hist_kernel<<<(Ee + 255)/256, 256>>>(ei);
    scan_kernel<<<1, 1024>>>();
    scatter_kernel<<<(Ee + 255)/256, 256>>>(ei);
    invdeg_kernel<<<(Nn + 255)/256, 256>>>(batch);

    transpose_split<<<dim3(STEPS*EHID, 4, 4), dim3(32, 32)>>>(nn_w2, p_w2t_hi, p_w2t_lo);
    transpose_split<<<dim3(STEPS, 4, 4),      dim3(32, 32)>>>(nn_b2, p_b2t_hi, p_b2t_lo);
    transpose_split<<<dim3(STEPS, 4, 4),      dim3(32, 32)>>>(root_w, p_rwt_hi, p_rwt_lo);
    split_kernel<<<(3*TILE + 255)/256, 256>>>(gru_wih, p_wih_hi, p_wih_lo, 3*TILE);
    split_kernel<<<(3*TILE + 255)/256, 256>>>(gru_whh, p_whh_hi, p_whh_lo, 3*TILE);

    for (int t = 0; t < STEPS; t++) {
        // u (32 tiles) + v (+agg zero) + gh (3 tiles), all from A = x
        gemm_step1<<<dim3(36, Nn/128), 256, SMEM_MMA>>>(t, gru_bhh);
        // per-source messages + scatter (edge MLP inline)
        msg_kernel<<<Nn, Hh>>>(ei, ea, nn_w1 + t*EHID, nn_b1 + t*EHID);
        // m = relu(agg*invdeg + x@root + b)  -> bf16 splits
        gemm_m<<<dim3(1, Nn/128), 256, SMEM_MMA>>>(t, conv_b + t*Hh);
        // gi = m @ wih^T + bih
        gemm_gi<<<dim3(3, Nn/128), 256, SMEM_MMA>>>(gru_bih);
        // GRU gate + split (+pool on last step)
        gate_kernel<<<(Nn*Hh + 255)/256, 256>>>(batch, t == STEPS - 1);
    }

    readout_kernel<<<1, 512>>>(lin1_w, lin1_b, lin2_w, lin2_b, out);
}